// round 5
// baseline (speedup 1.0000x reference)
#include <cuda_runtime.h>
#include <cuda_bf16.h>
#include <cstdint>
#include <cmath>

#define T_LEN 1024
#define NH    512
#define NI    128
#define BSZ   64
#define DT_C  0.1f

// Hoisted input projection scratch: tanh(x @ x2h), [B, T, H] fp32 (134 MB).
__device__ float g_tanhI[(size_t)BSZ * T_LEN * NH];

typedef unsigned long long ull;

// ---------------------------------------------------------------------------
// helpers
// ---------------------------------------------------------------------------
__device__ __forceinline__ uint32_t smem_u32(const void* p) {
    uint32_t a;
    asm("{ .reg .u64 t; cvta.to.shared.u64 t, %1; cvt.u32.u64 %0, t; }" : "=r"(a) : "l"(p));
    return a;
}
__device__ __forceinline__ uint32_t mapa_sc(uint32_t addr, uint32_t rank) {
    uint32_t r;
    asm("mapa.shared::cluster.u32 %0, %1, %2;" : "=r"(r) : "r"(addr), "r"(rank));
    return r;
}
__device__ __forceinline__ void st_dsm_v2(uint32_t addr, ull a, ull b) {
    asm volatile("st.shared::cluster.v2.b64 [%0], {%1, %2};"
                 :: "r"(addr), "l"(a), "l"(b) : "memory");
}
__device__ __forceinline__ void cluster_sync_() {
    asm volatile("barrier.cluster.arrive.aligned;" ::: "memory");
    asm volatile("barrier.cluster.wait.aligned;" ::: "memory");
}
__device__ __forceinline__ ull pack2(float w) {
    ull r;
    asm("mov.b64 %0, {%1, %1};" : "=l"(r) : "f"(w));
    return r;
}
__device__ __forceinline__ void ffma2(ull& d, ull a, ull b) {
    asm("fma.rn.f32x2 %0, %1, %2, %0;" : "+l"(d) : "l"(a), "l"(b));
}
__device__ __forceinline__ ull addf2(ull a, ull b) {
    ull d;
    asm("add.rn.f32x2 %0, %1, %2;" : "=l"(d) : "l"(a), "l"(b));
    return d;
}

// ---------------------------------------------------------------------------
// Phase 1: g_tanhI[bt, h] = tanh( x[bt, :] @ x2h[:, h] )
// ---------------------------------------------------------------------------
__global__ void __launch_bounds__(256) phase1_kernel(const float* __restrict__ x,
                                                     const float* __restrict__ x2h) {
    __shared__ float  x_s[16 * 132];
    __shared__ float4 w4_s[128 * 16];
    const int tid = threadIdx.x;
    const int bt0 = blockIdx.x * 16;

    for (int i = tid; i < 512; i += 256) {
        int r = i >> 5, c = i & 31;
        float4 v = *reinterpret_cast<const float4*>(x + (size_t)(bt0 + r) * NI + c * 4);
        *reinterpret_cast<float4*>(x_s + r * 132 + c * 4) = v;
    }

    const int tt = tid & 15;
    const int jc = tid >> 4;
    for (int chunk = 0; chunk < 8; ++chunk) {
        __syncthreads();
        const int jbase = chunk * 64;
        for (int i = tid; i < 2048; i += 256) {
            int k = i >> 4, jq = i & 15;
            w4_s[k * 16 + jq] =
                *reinterpret_cast<const float4*>(x2h + (size_t)k * NH + jbase + jq * 4);
        }
        __syncthreads();
        float a0 = 0.f, a1 = 0.f, a2 = 0.f, a3 = 0.f;
        #pragma unroll 8
        for (int k = 0; k < 128; ++k) {
            float  xv = x_s[tt * 132 + k];
            float4 w  = w4_s[k * 16 + jc];
            a0 = fmaf(xv, w.x, a0); a1 = fmaf(xv, w.y, a1);
            a2 = fmaf(xv, w.z, a2); a3 = fmaf(xv, w.w, a3);
        }
        float4 o = make_float4(tanhf(a0), tanhf(a1), tanhf(a2), tanhf(a3));
        *reinterpret_cast<float4*>(g_tanhI + (size_t)(bt0 + tt) * NH + jbase + jc * 4) = o;
    }
}

// ---------------------------------------------------------------------------
// Phase 2: recurrence. 16 clusters x 8 CTAs x 1024 threads (32 warps, occ 50%).
// CTA rank owns hidden cols J=[64r,64r+64); wT[j][k] resident, stride 513.
//
// SMEM float layout:
//   [0)      wT      64*513 = 32832
//   [32832)  hy4     512*4    (hy[k][m], 16B per k)
//   [34880)  pre     64*4     ([j][m], 16B per j)
//   [35136)  stage   16*64*4  (GEMM1 k-split partials [ks][j][m])
//   [39232)  red     8*64*4   (GEMM2 partials [src][kl][m])
//   [41280)  hyst    64*4     ([kl][m])
//   [41536)  bias    64
//   total 41600 floats = 166400 B
// ---------------------------------------------------------------------------
#define WS        513
#define W_OFF     0
#define HY_OFF    32832
#define PRE_OFF   34880
#define STG_OFF   35136
#define RED_OFF   39232
#define HYST_OFF  41280
#define BIAS_OFF  41536
#define SMEM_FLOATS 41600
#define SMEM_BYTES  (SMEM_FLOATS * 4)

__global__ void __launch_bounds__(1024)
rnn_kernel(const float* __restrict__ h2h, const float* __restrict__ bias,
           const float* __restrict__ gamma_v, const float* __restrict__ eps_v,
           float* __restrict__ out_states, float* __restrict__ out_hy) {
    extern __shared__ float sm[];
    float* bias_s = sm + BIAS_OFF;
    ulonglong2* stg2 = reinterpret_cast<ulonglong2*>(sm + STG_OFF);

    const int tid = threadIdx.x;
    uint32_t rank;
    asm("mov.u32 %0, %%cluster_ctarank;" : "=r"(rank));
    const int m_base = (blockIdx.x >> 3) * 4;
    const int J0 = (int)rank * 64;
    const uint32_t smb = smem_u32(sm);

    // --- init: weight slice wT[j][k] = h2h[k][J0+j], bias, zero hy ---
    for (int idx = tid; idx < 64 * 512; idx += 1024) {
        int k = idx >> 6, jl = idx & 63;
        sm[W_OFF + jl * WS + k] = h2h[(size_t)k * NH + J0 + jl];
    }
    if (tid < 64) bias_s[tid] = bias[J0 + tid];
    for (int i = tid; i < 2048; i += 1024) sm[HY_OFF + i] = 0.f;

    // --- fixed thread mappings ---
    const int ks = tid >> 6;          // GEMM1 k-split 0..15 (32 k each)
    const int jg = tid & 63;          // GEMM1 local j
    const int k2 = tid >> 1;          // GEMM2 k (0..511)
    const int jh = tid & 1;           // GEMM2 j-half
    // update mapping (tid < 256): flat [kl][m]
    const int kl_u = tid >> 2;
    const int m_u  = tid & 3;
    const int k_own = J0 + kl_u;

    // hoisted DSMEM addresses
    const uint32_t red_dst = mapa_sc(smb + RED_OFF * 4, (uint32_t)(k2 >> 6)) +
                             (uint32_t)((rank * 256 + (k2 & 63) * 4) * 4);
    const uint32_t hy_dst  = mapa_sc(smb + HY_OFF * 4, (uint32_t)(tid >> 6)) +
                             (uint32_t)((J0 + (tid & 63)) * 16);

    float hy_r = 0.f, hz_r = 0.f, g_r = 0.f, e_r = 0.f, tI = 0.f;
    size_t row_base = 0;
    if (tid < 256) {
        g_r = gamma_v[k_own];
        e_r = eps_v[k_own];
        row_base = (size_t)(m_base + m_u) * T_LEN * NH + k_own;
        tI = g_tanhI[row_base];
    }

    __syncthreads();
    cluster_sync_();

    const float* wcol1 = sm + W_OFF + jg * WS + ks * 32;
    const ulonglong2* hyk  = reinterpret_cast<const ulonglong2*>(sm + HY_OFF) + ks * 32;
    const ulonglong2* pre2 = reinterpret_cast<const ulonglong2*>(sm + PRE_OFF);
    const float* wcol2 = sm + W_OFF + jh * 32 * WS + k2;

    for (int t = 0; t < T_LEN; ++t) {
        // ---- GEMM1 k-split partial: stage[ks][jg][m0..3] ----
        {
            ull a01 = 0ull, a23 = 0ull;
            #pragma unroll 16
            for (int k = 0; k < 32; ++k) {
                ull w2 = pack2(wcol1[k]);
                ulonglong2 h = hyk[k];
                ffma2(a01, w2, h.x);
                ffma2(a23, w2, h.y);
            }
            stg2[ks * 64 + jg] = make_ulonglong2(a01, a23);
        }
        __syncthreads();
        if (tid < 256) {                 // sum 16 partials + bias + tanh
            float s = bias_s[tid >> 2];
            #pragma unroll
            for (int q = 0; q < 16; ++q) s += sm[STG_OFF + q * 256 + tid];
            sm[PRE_OFF + tid] = tanhf(s);
        }
        __syncthreads();

        // ---- GEMM2 partial over half j-slice; lanes pair on (k, jh) ----
        {
            ull b01 = 0ull, b23 = 0ull;
            #pragma unroll 16
            for (int j = 0; j < 32; ++j) {
                ull w2 = pack2(wcol2[j * WS]);
                ulonglong2 p = pre2[jh * 32 + j];
                ffma2(b01, w2, p.x);
                ffma2(b23, w2, p.y);
            }
            // combine j-halves: adjacent lanes (same k, jh 0/1)
            b01 = addf2(b01, __shfl_xor_sync(0xffffffffu, b01, 1));
            b23 = addf2(b23, __shfl_xor_sync(0xffffffffu, b23, 1));
            if (jh == 0)
                st_dsm_v2(red_dst, b01, b23);   // one 16B DSMEM store per k
        }
        cluster_sync_();                     // partials visible

        // ---- owner reduce + state update (tid < 256, flat [kl][m]) ----
        if (tid < 256) {
            int tn = (t + 1 < T_LEN) ? (t + 1) : (T_LEN - 1);
            float tI_next = g_tanhI[row_base + (size_t)tn * NH];

            float s = 0.f;
            #pragma unroll
            for (int src = 0; src < 8; ++src) s += sm[RED_OFF + src * 256 + tid];

            hz_r = hz_r + DT_C * (tI - s - g_r * hy_r - e_r * hz_r);
            hy_r = hy_r + DT_C * hz_r;
            tI = tI_next;

            out_states[(size_t)(m_base + m_u) * T_LEN * NH + (size_t)t * NH + k_own] = hy_r;
            sm[HYST_OFF + tid] = hy_r;       // [kl][m]
        }
        __syncthreads();

        // ---- broadcast new hy slice (tid < 512: 8 ranks x 64 k, 16B each) ----
        if (tid < 512) {
            ulonglong2 hv = *reinterpret_cast<const ulonglong2*>(
                sm + HYST_OFF + (tid & 63) * 4);
            st_dsm_v2(hy_dst, hv.x, hv.y);
        }
        cluster_sync_();                     // hy visible for next GEMM1
    }

    if (tid < 256 && out_hy)
        out_hy[(size_t)(m_base + m_u) * NH + k_own] = hy_r;
}

// ---------------------------------------------------------------------------
extern "C" void kernel_launch(void* const* d_in, const int* in_sizes, int n_in,
                              void* d_out, int out_size) {
    const float* x    = (const float*)d_in[0];
    const float* x2h  = (const float*)d_in[1];
    const float* h2h  = (const float*)d_in[2];
    const float* bias = (const float*)d_in[3];
    const float* gam  = (const float*)d_in[4];
    const float* eps  = (const float*)d_in[5];
    float* out = (float*)d_out;

    const long long BTH = (long long)BSZ * T_LEN * NH;
    float* states = nullptr;
    float* hyout  = nullptr;
    if ((long long)out_size >= BTH) {
        states = out;
        if ((long long)out_size >= BTH + (long long)BSZ * NH) hyout = out + BTH;
    } else {
        hyout = out;
    }

    phase1_kernel<<<(BSZ * T_LEN) / 16, 256>>>(x, x2h);

    cudaFuncSetAttribute(rnn_kernel, cudaFuncAttributeMaxDynamicSharedMemorySize,
                         SMEM_BYTES);

    cudaLaunchConfig_t cfg = {};
    cfg.gridDim = dim3(128, 1, 1);
    cfg.blockDim = dim3(1024, 1, 1);
    cfg.dynamicSmemBytes = SMEM_BYTES;
    cfg.stream = 0;
    cudaLaunchAttribute attrs[1];
    attrs[0].id = cudaLaunchAttributeClusterDimension;
    attrs[0].val.clusterDim.x = 8;
    attrs[0].val.clusterDim.y = 1;
    attrs[0].val.clusterDim.z = 1;
    cfg.attrs = attrs;
    cfg.numAttrs = 1;
    cudaLaunchKernelEx(&cfg, rnn_kernel, h2h, bias, gam, eps, states, hyout);
}

// round 6
// speedup vs baseline: 1.2576x; 1.2576x over previous
#include <cuda_runtime.h>
#include <cuda_bf16.h>
#include <cstdint>
#include <cmath>

#define T_LEN 1024
#define NH    512
#define NI    128
#define BSZ   64
#define DT_C  0.1f

// Hoisted input projection scratch: tanh(x @ x2h), [B, T, H] fp32 (134 MB).
__device__ float g_tanhI[(size_t)BSZ * T_LEN * NH];

typedef unsigned long long ull;

// ---------------------------------------------------------------------------
// helpers
// ---------------------------------------------------------------------------
__device__ __forceinline__ uint32_t smem_u32(const void* p) {
    uint32_t a;
    asm("{ .reg .u64 t; cvta.to.shared.u64 t, %1; cvt.u32.u64 %0, t; }" : "=r"(a) : "l"(p));
    return a;
}
__device__ __forceinline__ uint32_t mapa_sc(uint32_t addr, uint32_t rank) {
    uint32_t r;
    asm("mapa.shared::cluster.u32 %0, %1, %2;" : "=r"(r) : "r"(addr), "r"(rank));
    return r;
}
__device__ __forceinline__ void st_dsm_v2(uint32_t addr, ull a, ull b) {
    asm volatile("st.shared::cluster.v2.b64 [%0], {%1, %2};"
                 :: "r"(addr), "l"(a), "l"(b) : "memory");
}
__device__ __forceinline__ void cluster_sync_() {
    asm volatile("barrier.cluster.arrive.aligned;" ::: "memory");
    asm volatile("barrier.cluster.wait.aligned;" ::: "memory");
}
__device__ __forceinline__ ull pack2(float w) {
    ull r;
    asm("mov.b64 %0, {%1, %1};" : "=l"(r) : "f"(w));
    return r;
}
__device__ __forceinline__ void ffma2(ull& d, ull a, ull b) {
    asm("fma.rn.f32x2 %0, %1, %2, %0;" : "+l"(d) : "l"(a), "l"(b));
}
// mbarrier: remote release-arrive (cluster scope), local acquire parity wait
__device__ __forceinline__ void mbar_init(uint32_t addr, uint32_t count) {
    asm volatile("mbarrier.init.shared.b64 [%0], %1;" :: "r"(addr), "r"(count) : "memory");
}
__device__ __forceinline__ void mbar_arrive_remote(uint32_t addr) {
    asm volatile("mbarrier.arrive.release.cluster.shared::cluster.b64 _, [%0];"
                 :: "r"(addr) : "memory");
}
__device__ __forceinline__ void mbar_wait(uint32_t mbar, uint32_t parity) {
    uint32_t done;
    asm volatile(
        "{\n\t.reg .pred p;\n\t"
        "mbarrier.try_wait.parity.acquire.cluster.shared::cta.b64 p, [%1], %2;\n\t"
        "selp.b32 %0, 1, 0, p;\n\t}"
        : "=r"(done) : "r"(mbar), "r"(parity) : "memory");
    if (!done) {
        asm volatile(
            "{\n\t.reg .pred P1;\n\t"
            "W_%=:\n\t"
            "mbarrier.try_wait.parity.acquire.cluster.shared::cta.b64 P1, [%0], %1, 0x989680;\n\t"
            "@P1 bra.uni D_%=;\n\t"
            "bra.uni W_%=;\n\t"
            "D_%=:\n\t}"
            :: "r"(mbar), "r"(parity) : "memory");
    }
}

// ---------------------------------------------------------------------------
// Phase 1: g_tanhI[bt, h] = tanh( x[bt, :] @ x2h[:, h] )
// ---------------------------------------------------------------------------
__global__ void __launch_bounds__(256) phase1_kernel(const float* __restrict__ x,
                                                     const float* __restrict__ x2h) {
    __shared__ float  x_s[16 * 132];
    __shared__ float4 w4_s[128 * 16];
    const int tid = threadIdx.x;
    const int bt0 = blockIdx.x * 16;

    for (int i = tid; i < 512; i += 256) {
        int r = i >> 5, c = i & 31;
        float4 v = *reinterpret_cast<const float4*>(x + (size_t)(bt0 + r) * NI + c * 4);
        *reinterpret_cast<float4*>(x_s + r * 132 + c * 4) = v;
    }

    const int tt = tid & 15;
    const int jc = tid >> 4;
    for (int chunk = 0; chunk < 8; ++chunk) {
        __syncthreads();
        const int jbase = chunk * 64;
        for (int i = tid; i < 2048; i += 256) {
            int k = i >> 4, jq = i & 15;
            w4_s[k * 16 + jq] =
                *reinterpret_cast<const float4*>(x2h + (size_t)k * NH + jbase + jq * 4);
        }
        __syncthreads();
        float a0 = 0.f, a1 = 0.f, a2 = 0.f, a3 = 0.f;
        #pragma unroll 8
        for (int k = 0; k < 128; ++k) {
            float  xv = x_s[tt * 132 + k];
            float4 w  = w4_s[k * 16 + jc];
            a0 = fmaf(xv, w.x, a0); a1 = fmaf(xv, w.y, a1);
            a2 = fmaf(xv, w.z, a2); a3 = fmaf(xv, w.w, a3);
        }
        float4 o = make_float4(tanhf(a0), tanhf(a1), tanhf(a2), tanhf(a3));
        *reinterpret_cast<float4*>(g_tanhI + (size_t)(bt0 + tt) * NH + jbase + jc * 4) = o;
    }
}

// ---------------------------------------------------------------------------
// Phase 2: recurrence. 16 clusters x 8 CTAs x 512 threads (R3 structure),
// cluster barriers replaced by mbarrier release/acquire pipeline.
//
// SMEM float layout (R3):
//   [0)      wT      64*513 = 32832
//   [32832)  hy4     512*4
//   [34880)  pre     64*4
//   [35136)  stage   8*64*4
//   [37184)  red     8*64*4
//   [39232)  hyst    64*4
//   [39488)  bias    64
//   [39552)  mbars   red_mbar (8B), hy_mbar (8B)  -> 4 floats
//   total 39556 floats = 158224 B
// ---------------------------------------------------------------------------
#define WS        513
#define W_OFF     0
#define HY_OFF    32832
#define PRE_OFF   34880
#define STG_OFF   35136
#define RED_OFF   37184
#define HYST_OFF  39232
#define BIAS_OFF  39488
#define MBAR_OFF  39552
#define SMEM_FLOATS 39556
#define SMEM_BYTES  (SMEM_FLOATS * 4)

__global__ void __launch_bounds__(512)
rnn_kernel(const float* __restrict__ h2h, const float* __restrict__ bias,
           const float* __restrict__ gamma_v, const float* __restrict__ eps_v,
           float* __restrict__ out_states, float* __restrict__ out_hy) {
    extern __shared__ float sm[];
    float* bias_s = sm + BIAS_OFF;
    ulonglong2* stg2 = reinterpret_cast<ulonglong2*>(sm + STG_OFF);

    const int tid = threadIdx.x;
    uint32_t rank;
    asm("mov.u32 %0, %%cluster_ctarank;" : "=r"(rank));
    const int m_base = (blockIdx.x >> 3) * 4;
    const int J0 = (int)rank * 64;
    const uint32_t smb = smem_u32(sm);
    const uint32_t red_mbar = smb + MBAR_OFF * 4;
    const uint32_t hy_mbar  = smb + MBAR_OFF * 4 + 8;

    // --- init: weight slice wT[j][k] = h2h[k][J0+j], bias, zero hy, mbars ---
    for (int idx = tid; idx < 64 * 512; idx += 512) {
        int k = idx >> 6, jl = idx & 63;
        sm[W_OFF + jl * WS + k] = h2h[(size_t)k * NH + J0 + jl];
    }
    if (tid < 64) bias_s[tid] = bias[J0 + tid];
    for (int i = tid; i < 2048; i += 512) sm[HY_OFF + i] = 0.f;
    if (tid == 0) {
        mbar_init(red_mbar, 16);   // 2 warps x 8 CTAs arrive per phase
        mbar_init(hy_mbar, 16);
    }

    // --- fixed thread mappings (R3) ---
    const int ks = tid >> 6;          // GEMM1 k-split 0..7 (64 k each)
    const int jg = tid & 63;          // GEMM1 local j
    const int k2 = tid;               // GEMM2 k (0..511)
    const int kl_u = tid >> 2;        // update mapping (tid<256)
    const int m_u  = tid & 3;
    const int k_own = J0 + kl_u;

    // hoisted DSMEM data addresses + per-warp remote mbar addresses
    const uint32_t red_dst = mapa_sc(smb + RED_OFF * 4, (uint32_t)(k2 >> 6)) +
                             (uint32_t)((rank * 256 + (k2 & 63) * 4) * 4);
    const uint32_t hy_dst  = mapa_sc(smb + HY_OFF * 4, (uint32_t)(tid >> 6)) +
                             (uint32_t)((J0 + (tid & 63)) * 16);
    const uint32_t tgt_rank = (uint32_t)(tid >> 6);     // same for GEMM2 & bcast
    const uint32_t red_arr = mapa_sc(red_mbar, tgt_rank);
    const uint32_t hy_arr  = mapa_sc(hy_mbar, tgt_rank);
    const bool lane0 = (tid & 31) == 0;

    float hy_r = 0.f, hz_r = 0.f, g_r = 0.f, e_r = 0.f, tI = 0.f;
    size_t row_base = 0;
    if (tid < 256) {
        g_r = gamma_v[k_own];
        e_r = eps_v[k_own];
        row_base = (size_t)(m_base + m_u) * T_LEN * NH + k_own;
        tI = g_tanhI[row_base];
    }

    __syncthreads();
    cluster_sync_();   // mbars + weights visible cluster-wide before loop

    const float* wcol1 = sm + W_OFF + jg * WS + ks * 64;
    const ulonglong2* hyk  = reinterpret_cast<const ulonglong2*>(sm + HY_OFF) + ks * 64;
    const ulonglong2* pre2 = reinterpret_cast<const ulonglong2*>(sm + PRE_OFF);

    for (int t = 0; t < T_LEN; ++t) {
        const uint32_t par = (uint32_t)(t & 1);

        // ---- GEMM1 k-split partial: stage[ks][jg][m0..3] ----
        {
            ull a01 = 0ull, a23 = 0ull;
            #pragma unroll 16
            for (int k = 0; k < 64; ++k) {
                ull w2 = pack2(wcol1[k]);
                ulonglong2 h = hyk[k];
                ffma2(a01, w2, h.x);
                ffma2(a23, w2, h.y);
            }
            stg2[ks * 64 + jg] = make_ulonglong2(a01, a23);
        }
        __syncthreads();
        if (tid < 256) {                 // sum 8 partials + bias + tanh
            float s = bias_s[tid >> 2];
            #pragma unroll
            for (int q = 0; q < 8; ++q) s += sm[STG_OFF + q * 256 + tid];
            sm[PRE_OFF + tid] = tanhf(s);
        }
        __syncthreads();

        // ---- GEMM2 partial: 1 k per thread over my 64-j slice ----
        {
            ull b01 = 0ull, b23 = 0ull;
            #pragma unroll 16
            for (int j = 0; j < 64; ++j) {
                ull w2 = pack2(sm[W_OFF + j * WS + k2]);
                ulonglong2 p = pre2[j];
                ffma2(b01, w2, p.x);
                ffma2(b23, w2, p.y);
            }
            st_dsm_v2(red_dst, b01, b23);     // one 16B DSMEM store
            __syncwarp();
            if (lane0) mbar_arrive_remote(red_arr);
        }

        // ---- owner reduce + state update (tid < 256) ----
        if (tid < 256) {
            mbar_wait(red_mbar, par);         // all 16 red arrivals

            int tn = (t + 1 < T_LEN) ? (t + 1) : (T_LEN - 1);
            float tI_next = g_tanhI[row_base + (size_t)tn * NH];

            float s = 0.f;
            #pragma unroll
            for (int src = 0; src < 8; ++src) s += sm[RED_OFF + src * 256 + tid];

            hz_r = hz_r + DT_C * (tI - s - g_r * hy_r - e_r * hz_r);
            hy_r = hy_r + DT_C * hz_r;
            tI = tI_next;

            out_states[(size_t)(m_base + m_u) * T_LEN * NH + (size_t)t * NH + k_own] = hy_r;
            sm[HYST_OFF + tid] = hy_r;        // [kl][m]
        }
        __syncthreads();

        // ---- broadcast new hy slice (all 512 threads, 16B each) ----
        {
            ulonglong2 hv = *reinterpret_cast<const ulonglong2*>(
                sm + HYST_OFF + (tid & 63) * 4);
            st_dsm_v2(hy_dst, hv.x, hv.y);
            __syncwarp();
            if (lane0) mbar_arrive_remote(hy_arr);
        }
        mbar_wait(hy_mbar, par);              // hy complete -> next GEMM1
    }

    if (tid < 256 && out_hy)
        out_hy[(size_t)(m_base + m_u) * NH + k_own] = hy_r;
}

// ---------------------------------------------------------------------------
extern "C" void kernel_launch(void* const* d_in, const int* in_sizes, int n_in,
                              void* d_out, int out_size) {
    const float* x    = (const float*)d_in[0];
    const float* x2h  = (const float*)d_in[1];
    const float* h2h  = (const float*)d_in[2];
    const float* bias = (const float*)d_in[3];
    const float* gam  = (const float*)d_in[4];
    const float* eps  = (const float*)d_in[5];
    float* out = (float*)d_out;

    const long long BTH = (long long)BSZ * T_LEN * NH;
    float* states = nullptr;
    float* hyout  = nullptr;
    if ((long long)out_size >= BTH) {
        states = out;
        if ((long long)out_size >= BTH + (long long)BSZ * NH) hyout = out + BTH;
    } else {
        hyout = out;
    }

    phase1_kernel<<<(BSZ * T_LEN) / 16, 256>>>(x, x2h);

    cudaFuncSetAttribute(rnn_kernel, cudaFuncAttributeMaxDynamicSharedMemorySize,
                         SMEM_BYTES);

    cudaLaunchConfig_t cfg = {};
    cfg.gridDim = dim3(128, 1, 1);
    cfg.blockDim = dim3(512, 1, 1);
    cfg.dynamicSmemBytes = SMEM_BYTES;
    cfg.stream = 0;
    cudaLaunchAttribute attrs[1];
    attrs[0].id = cudaLaunchAttributeClusterDimension;
    attrs[0].val.clusterDim.x = 8;
    attrs[0].val.clusterDim.y = 1;
    attrs[0].val.clusterDim.z = 1;
    cfg.attrs = attrs;
    cfg.numAttrs = 1;
    cudaLaunchKernelEx(&cfg, rnn_kernel, h2h, bias, gam, eps, states, hyout);
}

// round 7
// speedup vs baseline: 1.2737x; 1.0128x over previous
#include <cuda_runtime.h>
#include <cuda_bf16.h>
#include <cstdint>
#include <cmath>

#define T_LEN 1024
#define NH    512
#define NI    128
#define BSZ   64
#define DT_C  0.1f

// Hoisted input projection scratch: tanh(x @ x2h), [B, T, H] fp32 (134 MB).
__device__ float g_tanhI[(size_t)BSZ * T_LEN * NH];

typedef unsigned long long ull;

// ---------------------------------------------------------------------------
// helpers
// ---------------------------------------------------------------------------
__device__ __forceinline__ uint32_t smem_u32(const void* p) {
    uint32_t a;
    asm("{ .reg .u64 t; cvta.to.shared.u64 t, %1; cvt.u32.u64 %0, t; }" : "=r"(a) : "l"(p));
    return a;
}
__device__ __forceinline__ uint32_t mapa_sc(uint32_t addr, uint32_t rank) {
    uint32_t r;
    asm("mapa.shared::cluster.u32 %0, %1, %2;" : "=r"(r) : "r"(addr), "r"(rank));
    return r;
}
__device__ __forceinline__ void st_dsm_v2(uint32_t addr, ull a, ull b) {
    asm volatile("st.shared::cluster.v2.b64 [%0], {%1, %2};"
                 :: "r"(addr), "l"(a), "l"(b) : "memory");
}
__device__ __forceinline__ void cluster_sync_() {
    asm volatile("barrier.cluster.arrive.aligned;" ::: "memory");
    asm volatile("barrier.cluster.wait.aligned;" ::: "memory");
}
__device__ __forceinline__ ull pack2(float w) {
    ull r;
    asm("mov.b64 %0, {%1, %1};" : "=l"(r) : "f"(w));
    return r;
}
__device__ __forceinline__ void ffma2(ull& d, ull a, ull b) {
    asm("fma.rn.f32x2 %0, %1, %2, %0;" : "+l"(d) : "l"(a), "l"(b));
}
__device__ __forceinline__ void mbar_init(uint32_t addr, uint32_t count) {
    asm volatile("mbarrier.init.shared.b64 [%0], %1;" :: "r"(addr), "r"(count) : "memory");
}
__device__ __forceinline__ void mbar_arrive_remote(uint32_t addr) {
    asm volatile("mbarrier.arrive.release.cluster.shared::cluster.b64 _, [%0];"
                 :: "r"(addr) : "memory");
}
__device__ __forceinline__ void mbar_wait(uint32_t mbar, uint32_t parity) {
    uint32_t done;
    asm volatile(
        "{\n\t.reg .pred p;\n\t"
        "mbarrier.try_wait.parity.acquire.cluster.shared::cta.b64 p, [%1], %2;\n\t"
        "selp.b32 %0, 1, 0, p;\n\t}"
        : "=r"(done) : "r"(mbar), "r"(parity) : "memory");
    if (!done) {
        asm volatile(
            "{\n\t.reg .pred P1;\n\t"
            "W_%=:\n\t"
            "mbarrier.try_wait.parity.acquire.cluster.shared::cta.b64 P1, [%0], %1, 0x989680;\n\t"
            "@P1 bra.uni D_%=;\n\t"
            "bra.uni W_%=;\n\t"
            "D_%=:\n\t}"
            :: "r"(mbar), "r"(parity) : "memory");
    }
}

// ---------------------------------------------------------------------------
// Phase 1: g_tanhI[bt, h] = tanh( x[bt, :] @ x2h[:, h] )
// ---------------------------------------------------------------------------
__global__ void __launch_bounds__(256) phase1_kernel(const float* __restrict__ x,
                                                     const float* __restrict__ x2h) {
    __shared__ float  x_s[16 * 132];
    __shared__ float4 w4_s[128 * 16];
    const int tid = threadIdx.x;
    const int bt0 = blockIdx.x * 16;

    for (int i = tid; i < 512; i += 256) {
        int r = i >> 5, c = i & 31;
        float4 v = *reinterpret_cast<const float4*>(x + (size_t)(bt0 + r) * NI + c * 4);
        *reinterpret_cast<float4*>(x_s + r * 132 + c * 4) = v;
    }

    const int tt = tid & 15;
    const int jc = tid >> 4;
    for (int chunk = 0; chunk < 8; ++chunk) {
        __syncthreads();
        const int jbase = chunk * 64;
        for (int i = tid; i < 2048; i += 256) {
            int k = i >> 4, jq = i & 15;
            w4_s[k * 16 + jq] =
                *reinterpret_cast<const float4*>(x2h + (size_t)k * NH + jbase + jq * 4);
        }
        __syncthreads();
        float a0 = 0.f, a1 = 0.f, a2 = 0.f, a3 = 0.f;
        #pragma unroll 8
        for (int k = 0; k < 128; ++k) {
            float  xv = x_s[tt * 132 + k];
            float4 w  = w4_s[k * 16 + jc];
            a0 = fmaf(xv, w.x, a0); a1 = fmaf(xv, w.y, a1);
            a2 = fmaf(xv, w.z, a2); a3 = fmaf(xv, w.w, a3);
        }
        float4 o = make_float4(tanhf(a0), tanhf(a1), tanhf(a2), tanhf(a3));
        *reinterpret_cast<float4*>(g_tanhI + (size_t)(bt0 + tt) * NH + jbase + jc * 4) = o;
    }
}

// ---------------------------------------------------------------------------
// Phase 2: recurrence. 16 clusters x 8 CTAs x 512 threads.
// R3 compute structure; all in-loop cluster-wide barriers replaced by
// fine-grained per-source mbarriers (red_mbar[8], hy_mbar[8]).
//
// SMEM float layout:
//   [0)      wT      64*513 = 32832
//   [32832)  hy4     512*4
//   [34880)  pre     64*4
//   [35136)  stage   8*64*4
//   [37184)  red     8*64*4   ([src][kl][m])
//   [39232)  hyst    64*4     ([kl][m])
//   [39488)  bias    64
//   [39552)  mbars   red_mbar[8] (64B) + hy_mbar[8] (64B) = 32 floats
//   total 39584 floats = 158336 B
// ---------------------------------------------------------------------------
#define WS        513
#define W_OFF     0
#define HY_OFF    32832
#define PRE_OFF   34880
#define STG_OFF   35136
#define RED_OFF   37184
#define HYST_OFF  39232
#define BIAS_OFF  39488
#define MBAR_OFF  39552
#define SMEM_FLOATS 39584
#define SMEM_BYTES  (SMEM_FLOATS * 4)

__global__ void __launch_bounds__(512)
rnn_kernel(const float* __restrict__ h2h, const float* __restrict__ bias,
           const float* __restrict__ gamma_v, const float* __restrict__ eps_v,
           float* __restrict__ out_states, float* __restrict__ out_hy) {
    extern __shared__ float sm[];
    float* bias_s = sm + BIAS_OFF;
    ulonglong2* stg2 = reinterpret_cast<ulonglong2*>(sm + STG_OFF);

    const int tid = threadIdx.x;
    uint32_t rank;
    asm("mov.u32 %0, %%cluster_ctarank;" : "=r"(rank));
    const int m_base = (blockIdx.x >> 3) * 4;
    const int J0 = (int)rank * 64;
    const uint32_t smb = smem_u32(sm);
    const uint32_t red_mbar_base = smb + MBAR_OFF * 4;        // red_mbar[8]
    const uint32_t hy_mbar_base  = smb + MBAR_OFF * 4 + 64;   // hy_mbar[8]

    // --- init: weight slice wT[j][k] = h2h[k][J0+j], bias, zero hy, mbars ---
    for (int idx = tid; idx < 64 * 512; idx += 512) {
        int k = idx >> 6, jl = idx & 63;
        sm[W_OFF + jl * WS + k] = h2h[(size_t)k * NH + J0 + jl];
    }
    if (tid < 64) bias_s[tid] = bias[J0 + tid];
    for (int i = tid; i < 2048; i += 512) sm[HY_OFF + i] = 0.f;
    if (tid < 8) {
        mbar_init(red_mbar_base + tid * 8, 2);   // 2 warps from source tid
        mbar_init(hy_mbar_base + tid * 8, 2);    // 2 sender warps from source tid
    }

    // --- fixed thread mappings (R3) ---
    const int ks = tid >> 6;          // GEMM1 k-chunk 0..7 (64 k each; warp-uniform)
    const int jg = tid & 63;          // GEMM1 local j
    const int k2 = tid;               // GEMM2 k (0..511)
    const int kl_u = tid >> 2;        // update mapping (tid<256)
    const int m_u  = tid & 3;
    const int k_own = J0 + kl_u;

    // hoisted DSMEM data + remote mbar addresses
    const uint32_t red_tgt = (uint32_t)(k2 >> 6);
    const uint32_t red_dst = mapa_sc(smb + RED_OFF * 4, red_tgt) +
                             (uint32_t)((rank * 256 + (k2 & 63) * 4) * 4);
    const uint32_t red_arr = mapa_sc(red_mbar_base + rank * 8, red_tgt);
    const uint32_t hy_tgt  = (uint32_t)(tid >> 6);
    const uint32_t hy_dst  = mapa_sc(smb + HY_OFF * 4, hy_tgt) +
                             (uint32_t)((J0 + (tid & 63)) * 16);
    const uint32_t hy_arr  = mapa_sc(hy_mbar_base + rank * 8, hy_tgt);
    const uint32_t hy_wait = hy_mbar_base + (uint32_t)ks * 8;  // my chunk's mbar
    const bool lane0 = (tid & 31) == 0;

    float hy_r = 0.f, hz_r = 0.f, g_r = 0.f, e_r = 0.f, tI = 0.f;
    size_t row_base = 0;
    if (tid < 256) {
        g_r = gamma_v[k_own];
        e_r = eps_v[k_own];
        row_base = (size_t)(m_base + m_u) * T_LEN * NH + k_own;
        tI = g_tanhI[row_base];
    }

    __syncthreads();
    cluster_sync_();   // mbars + weights + zeroed hy visible cluster-wide

    const float* wcol1 = sm + W_OFF + jg * WS + ks * 64;
    const ulonglong2* hyk  = reinterpret_cast<const ulonglong2*>(sm + HY_OFF) + ks * 64;
    const ulonglong2* pre2 = reinterpret_cast<const ulonglong2*>(sm + PRE_OFF);

    for (int t = 0; t < T_LEN; ++t) {
        // ---- wait only MY hy chunk (warp-uniform), then GEMM1 partial ----
        if (t) mbar_wait(hy_wait, (uint32_t)((t + 1) & 1));
        {
            ull a01 = 0ull, a23 = 0ull;
            #pragma unroll 16
            for (int k = 0; k < 64; ++k) {
                ull w2 = pack2(wcol1[k]);
                ulonglong2 h = hyk[k];
                ffma2(a01, w2, h.x);
                ffma2(a23, w2, h.y);
            }
            stg2[ks * 64 + jg] = make_ulonglong2(a01, a23);
        }
        __syncthreads();
        if (tid < 256) {                 // sum 8 partials + bias + tanh
            float s = bias_s[tid >> 2];
            #pragma unroll
            for (int q = 0; q < 8; ++q) s += sm[STG_OFF + q * 256 + tid];
            sm[PRE_OFF + tid] = tanhf(s);
        }
        __syncthreads();

        // ---- GEMM2 partial: 1 k per thread over my 64-j slice; scatter ----
        {
            ull b01 = 0ull, b23 = 0ull;
            #pragma unroll 16
            for (int j = 0; j < 64; ++j) {
                ull w2 = pack2(sm[W_OFF + j * WS + k2]);
                ulonglong2 p = pre2[j];
                ffma2(b01, w2, p.x);
                ffma2(b23, w2, p.y);
            }
            st_dsm_v2(red_dst, b01, b23);     // one 16B DSMEM store
            __syncwarp();
            if (lane0) mbar_arrive_remote(red_arr);
        }

        // ---- owner update: consume per-source partials as they arrive ----
        if (tid < 256) {
            int tn = (t + 1 < T_LEN) ? (t + 1) : (T_LEN - 1);
            float tI_next = g_tanhI[row_base + (size_t)tn * NH];

            float s = 0.f;
            #pragma unroll
            for (int src = 0; src < 8; ++src) {
                mbar_wait(red_mbar_base + src * 8, (uint32_t)(t & 1));
                s += sm[RED_OFF + src * 256 + tid];
            }

            hz_r = hz_r + DT_C * (tI - s - g_r * hy_r - e_r * hz_r);
            hy_r = hy_r + DT_C * hz_r;
            tI = tI_next;

            out_states[(size_t)(m_base + m_u) * T_LEN * NH + (size_t)t * NH + k_own] = hy_r;
            sm[HYST_OFF + tid] = hy_r;        // [kl][m]
        }
        __syncthreads();

        // ---- broadcast new hy slice (skip after last step) ----
        if (t + 1 < T_LEN) {
            ulonglong2 hv = *reinterpret_cast<const ulonglong2*>(
                sm + HYST_OFF + (tid & 63) * 4);
            st_dsm_v2(hy_dst, hv.x, hv.y);
            __syncwarp();
            if (lane0) mbar_arrive_remote(hy_arr);
        }
    }

    if (tid < 256 && out_hy)
        out_hy[(size_t)(m_base + m_u) * NH + k_own] = hy_r;

    cluster_sync_();   // no CTA exits while peers' DSMEM traffic may target it
}

// ---------------------------------------------------------------------------
extern "C" void kernel_launch(void* const* d_in, const int* in_sizes, int n_in,
                              void* d_out, int out_size) {
    const float* x    = (const float*)d_in[0];
    const float* x2h  = (const float*)d_in[1];
    const float* h2h  = (const float*)d_in[2];
    const float* bias = (const float*)d_in[3];
    const float* gam  = (const float*)d_in[4];
    const float* eps  = (const float*)d_in[5];
    float* out = (float*)d_out;

    const long long BTH = (long long)BSZ * T_LEN * NH;
    float* states = nullptr;
    float* hyout  = nullptr;
    if ((long long)out_size >= BTH) {
        states = out;
        if ((long long)out_size >= BTH + (long long)BSZ * NH) hyout = out + BTH;
    } else {
        hyout = out;
    }

    phase1_kernel<<<(BSZ * T_LEN) / 16, 256>>>(x, x2h);

    cudaFuncSetAttribute(rnn_kernel, cudaFuncAttributeMaxDynamicSharedMemorySize,
                         SMEM_BYTES);

    cudaLaunchConfig_t cfg = {};
    cfg.gridDim = dim3(128, 1, 1);
    cfg.blockDim = dim3(512, 1, 1);
    cfg.dynamicSmemBytes = SMEM_BYTES;
    cfg.stream = 0;
    cudaLaunchAttribute attrs[1];
    attrs[0].id = cudaLaunchAttributeClusterDimension;
    attrs[0].val.clusterDim.x = 8;
    attrs[0].val.clusterDim.y = 1;
    attrs[0].val.clusterDim.z = 1;
    cfg.attrs = attrs;
    cfg.numAttrs = 1;
    cudaLaunchKernelEx(&cfg, rnn_kernel, h2h, bias, gam, eps, states, hyout);
}

// round 8
// speedup vs baseline: 1.3421x; 1.0537x over previous
#include <cuda_runtime.h>
#include <cuda_bf16.h>
#include <cstdint>
#include <cmath>

#define T_LEN 1024
#define NH    512
#define NI    128
#define BSZ   64
#define DT_C  0.1f

// Hoisted input projection scratch: tanh(x @ x2h), [B, T, H] fp32 (134 MB).
__device__ float g_tanhI[(size_t)BSZ * T_LEN * NH];

typedef unsigned long long ull;

// ---------------------------------------------------------------------------
// helpers
// ---------------------------------------------------------------------------
__device__ __forceinline__ uint32_t smem_u32(const void* p) {
    uint32_t a;
    asm("{ .reg .u64 t; cvta.to.shared.u64 t, %1; cvt.u32.u64 %0, t; }" : "=r"(a) : "l"(p));
    return a;
}
__device__ __forceinline__ uint32_t mapa_sc(uint32_t addr, uint32_t rank) {
    uint32_t r;
    asm("mapa.shared::cluster.u32 %0, %1, %2;" : "=r"(r) : "r"(addr), "r"(rank));
    return r;
}
__device__ __forceinline__ void st_dsm_v2(uint32_t addr, ull a, ull b) {
    asm volatile("st.shared::cluster.v2.b64 [%0], {%1, %2};"
                 :: "r"(addr), "l"(a), "l"(b) : "memory");
}
__device__ __forceinline__ void cluster_sync_() {
    asm volatile("barrier.cluster.arrive.aligned;" ::: "memory");
    asm volatile("barrier.cluster.wait.aligned;" ::: "memory");
}
__device__ __forceinline__ ull pack2(float w) {
    ull r;
    asm("mov.b64 %0, {%1, %1};" : "=l"(r) : "f"(w));
    return r;
}
__device__ __forceinline__ void ffma2(ull& d, ull a, ull b) {
    asm("fma.rn.f32x2 %0, %1, %2, %0;" : "+l"(d) : "l"(a), "l"(b));
}

// ---------------------------------------------------------------------------
// Phase 1: g_tanhI[bt, h] = tanh( x[bt, :] @ x2h[:, h] )
// ---------------------------------------------------------------------------
__global__ void __launch_bounds__(256) phase1_kernel(const float* __restrict__ x,
                                                     const float* __restrict__ x2h) {
    __shared__ float  x_s[16 * 132];
    __shared__ float4 w4_s[128 * 16];
    const int tid = threadIdx.x;
    const int bt0 = blockIdx.x * 16;

    for (int i = tid; i < 512; i += 256) {
        int r = i >> 5, c = i & 31;
        float4 v = *reinterpret_cast<const float4*>(x + (size_t)(bt0 + r) * NI + c * 4);
        *reinterpret_cast<float4*>(x_s + r * 132 + c * 4) = v;
    }

    const int tt = tid & 15;
    const int jc = tid >> 4;
    for (int chunk = 0; chunk < 8; ++chunk) {
        __syncthreads();
        const int jbase = chunk * 64;
        for (int i = tid; i < 2048; i += 256) {
            int k = i >> 4, jq = i & 15;
            w4_s[k * 16 + jq] =
                *reinterpret_cast<const float4*>(x2h + (size_t)k * NH + jbase + jq * 4);
        }
        __syncthreads();
        float a0 = 0.f, a1 = 0.f, a2 = 0.f, a3 = 0.f;
        #pragma unroll 8
        for (int k = 0; k < 128; ++k) {
            float  xv = x_s[tt * 132 + k];
            float4 w  = w4_s[k * 16 + jc];
            a0 = fmaf(xv, w.x, a0); a1 = fmaf(xv, w.y, a1);
            a2 = fmaf(xv, w.z, a2); a3 = fmaf(xv, w.w, a3);
        }
        float4 o = make_float4(tanhf(a0), tanhf(a1), tanhf(a2), tanhf(a3));
        *reinterpret_cast<float4*>(g_tanhI + (size_t)(bt0 + tt) * NH + jbase + jc * 4) = o;
    }
}

// ---------------------------------------------------------------------------
// Phase 2: recurrence. 16 clusters x 8 CTAs x 512 threads (R3 skeleton).
// This round: GEMM inner loops rewritten as explicit depth-8 double-buffered
// register pipelines to force MLP (ptxas previously allocated only 32 regs,
// exposing LDS latency on every FMA chain).
//
// SMEM float layout (R3):
//   [0)      wT      64*513 = 32832
//   [32832)  hy4     512*4
//   [34880)  pre     64*4
//   [35136)  stage   8*64*4
//   [37184)  red     8*64*4
//   [39232)  hyst    64*4
//   [39488)  bias    64
//   total 39552 floats = 158208 B
// ---------------------------------------------------------------------------
#define WS        513
#define W_OFF     0
#define HY_OFF    32832
#define PRE_OFF   34880
#define STG_OFF   35136
#define RED_OFF   37184
#define HYST_OFF  39232
#define BIAS_OFF  39488
#define SMEM_FLOATS 39552
#define SMEM_BYTES  (SMEM_FLOATS * 4)

__global__ void __launch_bounds__(512)
rnn_kernel(const float* __restrict__ h2h, const float* __restrict__ bias,
           const float* __restrict__ gamma_v, const float* __restrict__ eps_v,
           float* __restrict__ out_states, float* __restrict__ out_hy) {
    extern __shared__ float sm[];
    float* bias_s = sm + BIAS_OFF;
    ulonglong2* stg2 = reinterpret_cast<ulonglong2*>(sm + STG_OFF);

    const int tid = threadIdx.x;
    uint32_t rank;
    asm("mov.u32 %0, %%cluster_ctarank;" : "=r"(rank));
    const int m_base = (blockIdx.x >> 3) * 4;
    const int J0 = (int)rank * 64;
    const uint32_t smb = smem_u32(sm);

    // --- init: weight slice wT[j][k] = h2h[k][J0+j], bias, zero hy ---
    for (int idx = tid; idx < 64 * 512; idx += 512) {
        int k = idx >> 6, jl = idx & 63;
        sm[W_OFF + jl * WS + k] = h2h[(size_t)k * NH + J0 + jl];
    }
    if (tid < 64) bias_s[tid] = bias[J0 + tid];
    for (int i = tid; i < 2048; i += 512) sm[HY_OFF + i] = 0.f;

    // --- fixed thread mappings (R3) ---
    const int ks = tid >> 6;          // GEMM1 k-split 0..7 (64 k each)
    const int jg = tid & 63;          // GEMM1 local j
    const int k2 = tid;               // GEMM2 k (0..511)
    const int kl_u = tid >> 2;        // update mapping (tid<256)
    const int m_u  = tid & 3;
    const int k_own = J0 + kl_u;

    // hoisted DSMEM addresses
    const uint32_t red_dst = mapa_sc(smb + RED_OFF * 4, (uint32_t)(k2 >> 6)) +
                             (uint32_t)((rank * 256 + (k2 & 63) * 4) * 4);
    const uint32_t hy_dst  = mapa_sc(smb + HY_OFF * 4, (uint32_t)(tid >> 6)) +
                             (uint32_t)((J0 + (tid & 63)) * 16);

    float hy_r = 0.f, hz_r = 0.f, g_r = 0.f, e_r = 0.f, tI = 0.f;
    size_t row_base = 0;
    if (tid < 256) {
        g_r = gamma_v[k_own];
        e_r = eps_v[k_own];
        row_base = (size_t)(m_base + m_u) * T_LEN * NH + k_own;
        tI = g_tanhI[row_base];
    }

    __syncthreads();
    cluster_sync_();

    const float* wcol1 = sm + W_OFF + jg * WS + ks * 64;
    const ulonglong2* hyk  = reinterpret_cast<const ulonglong2*>(sm + HY_OFF) + ks * 64;
    const ulonglong2* pre2 = reinterpret_cast<const ulonglong2*>(sm + PRE_OFF);
    const float* wrow2 = sm + W_OFF + k2;

    for (int t = 0; t < T_LEN; ++t) {
        // ---- GEMM1 k-split partial, depth-8 double-buffered pipeline ----
        {
            ull a01 = 0ull, a23 = 0ull;
            float wb[2][8];
            ulonglong2 hb[2][8];
            #pragma unroll
            for (int i = 0; i < 8; ++i) { wb[0][i] = wcol1[i]; hb[0][i] = hyk[i]; }
            #pragma unroll
            for (int blk = 0; blk < 8; ++blk) {
                const int cur = blk & 1, nxt = cur ^ 1;
                if (blk < 7) {
                    const int base = (blk + 1) * 8;
                    #pragma unroll
                    for (int i = 0; i < 8; ++i) {
                        wb[nxt][i] = wcol1[base + i];
                        hb[nxt][i] = hyk[base + i];
                    }
                }
                #pragma unroll
                for (int i = 0; i < 8; ++i) {
                    ull w2 = pack2(wb[cur][i]);
                    ffma2(a01, w2, hb[cur][i].x);
                    ffma2(a23, w2, hb[cur][i].y);
                }
            }
            stg2[ks * 64 + jg] = make_ulonglong2(a01, a23);
        }
        __syncthreads();
        if (tid < 256) {                 // sum 8 partials + bias + tanh
            float s = bias_s[tid >> 2];
            #pragma unroll
            for (int q = 0; q < 8; ++q) s += sm[STG_OFF + q * 256 + tid];
            sm[PRE_OFF + tid] = tanhf(s);
        }
        __syncthreads();

        // ---- GEMM2 partial, depth-8 double-buffered pipeline ----
        {
            ull b01 = 0ull, b23 = 0ull;
            float wb[2][8];
            ulonglong2 pb[2][8];
            #pragma unroll
            for (int i = 0; i < 8; ++i) { wb[0][i] = wrow2[i * WS]; pb[0][i] = pre2[i]; }
            #pragma unroll
            for (int blk = 0; blk < 8; ++blk) {
                const int cur = blk & 1, nxt = cur ^ 1;
                if (blk < 7) {
                    const int base = (blk + 1) * 8;
                    #pragma unroll
                    for (int i = 0; i < 8; ++i) {
                        wb[nxt][i] = wrow2[(base + i) * WS];
                        pb[nxt][i] = pre2[base + i];
                    }
                }
                #pragma unroll
                for (int i = 0; i < 8; ++i) {
                    ull w2 = pack2(wb[cur][i]);
                    ffma2(b01, w2, pb[cur][i].x);
                    ffma2(b23, w2, pb[cur][i].y);
                }
            }
            st_dsm_v2(red_dst, b01, b23);     // one 16B DSMEM store
        }
        cluster_sync_();                     // partials visible

        // ---- owner reduce + state update (tid < 256) ----
        if (tid < 256) {
            int tn = (t + 1 < T_LEN) ? (t + 1) : (T_LEN - 1);
            float tI_next = g_tanhI[row_base + (size_t)tn * NH];

            float s = 0.f;
            #pragma unroll
            for (int src = 0; src < 8; ++src) s += sm[RED_OFF + src * 256 + tid];

            hz_r = hz_r + DT_C * (tI - s - g_r * hy_r - e_r * hz_r);
            hy_r = hy_r + DT_C * hz_r;
            tI = tI_next;

            out_states[(size_t)(m_base + m_u) * T_LEN * NH + (size_t)t * NH + k_own] = hy_r;
            sm[HYST_OFF + tid] = hy_r;       // [kl][m]
        }
        __syncthreads();

        // ---- broadcast new hy slice (all 512 threads, 16B each) ----
        {
            ulonglong2 hv = *reinterpret_cast<const ulonglong2*>(
                sm + HYST_OFF + (tid & 63) * 4);
            st_dsm_v2(hy_dst, hv.x, hv.y);
        }
        cluster_sync_();                     // hy visible for next GEMM1
    }

    if (tid < 256 && out_hy)
        out_hy[(size_t)(m_base + m_u) * NH + k_own] = hy_r;
}

// ---------------------------------------------------------------------------
extern "C" void kernel_launch(void* const* d_in, const int* in_sizes, int n_in,
                              void* d_out, int out_size) {
    const float* x    = (const float*)d_in[0];
    const float* x2h  = (const float*)d_in[1];
    const float* h2h  = (const float*)d_in[2];
    const float* bias = (const float*)d_in[3];
    const float* gam  = (const float*)d_in[4];
    const float* eps  = (const float*)d_in[5];
    float* out = (float*)d_out;

    const long long BTH = (long long)BSZ * T_LEN * NH;
    float* states = nullptr;
    float* hyout  = nullptr;
    if ((long long)out_size >= BTH) {
        states = out;
        if ((long long)out_size >= BTH + (long long)BSZ * NH) hyout = out + BTH;
    } else {
        hyout = out;
    }

    phase1_kernel<<<(BSZ * T_LEN) / 16, 256>>>(x, x2h);

    cudaFuncSetAttribute(rnn_kernel, cudaFuncAttributeMaxDynamicSharedMemorySize,
                         SMEM_BYTES);

    cudaLaunchConfig_t cfg = {};
    cfg.gridDim = dim3(128, 1, 1);
    cfg.blockDim = dim3(512, 1, 1);
    cfg.dynamicSmemBytes = SMEM_BYTES;
    cfg.stream = 0;
    cudaLaunchAttribute attrs[1];
    attrs[0].id = cudaLaunchAttributeClusterDimension;
    attrs[0].val.clusterDim.x = 8;
    attrs[0].val.clusterDim.y = 1;
    attrs[0].val.clusterDim.z = 1;
    cfg.attrs = attrs;
    cfg.numAttrs = 1;
    cudaLaunchKernelEx(&cfg, rnn_kernel, h2h, bias, gam, eps, states, hyout);
}

// round 9
// speedup vs baseline: 1.3635x; 1.0160x over previous
#include <cuda_runtime.h>
#include <cuda_bf16.h>
#include <cstdint>
#include <cmath>

#define T_LEN 1024
#define NH    512
#define NI    128
#define BSZ   64
#define DT_C  0.1f

// Hoisted input projection scratch: tanh(x @ x2h), [B, T, H] fp32 (134 MB).
__device__ float g_tanhI[(size_t)BSZ * T_LEN * NH];

typedef unsigned long long ull;

// ---------------------------------------------------------------------------
// helpers
// ---------------------------------------------------------------------------
__device__ __forceinline__ uint32_t smem_u32(const void* p) {
    uint32_t a;
    asm("{ .reg .u64 t; cvta.to.shared.u64 t, %1; cvt.u32.u64 %0, t; }" : "=r"(a) : "l"(p));
    return a;
}
__device__ __forceinline__ uint32_t mapa_sc(uint32_t addr, uint32_t rank) {
    uint32_t r;
    asm("mapa.shared::cluster.u32 %0, %1, %2;" : "=r"(r) : "r"(addr), "r"(rank));
    return r;
}
__device__ __forceinline__ void st_dsm_v2(uint32_t addr, ull a, ull b) {
    asm volatile("st.shared::cluster.v2.b64 [%0], {%1, %2};"
                 :: "r"(addr), "l"(a), "l"(b) : "memory");
}
__device__ __forceinline__ void cluster_sync_() {
    asm volatile("barrier.cluster.arrive.aligned;" ::: "memory");
    asm volatile("barrier.cluster.wait.aligned;" ::: "memory");
}
__device__ __forceinline__ ull pack2(float w) {
    ull r;
    asm("mov.b64 %0, {%1, %1};" : "=l"(r) : "f"(w));
    return r;
}
__device__ __forceinline__ void unpack2(float& lo, float& hi, ull v) {
    asm("mov.b64 {%0, %1}, %2;" : "=f"(lo), "=f"(hi) : "l"(v));
}
__device__ __forceinline__ void ffma2(ull& d, ull a, ull b) {
    asm("fma.rn.f32x2 %0, %1, %2, %0;" : "+l"(d) : "l"(a), "l"(b));
}
__device__ __forceinline__ ull addf2(ull a, ull b) {
    ull d;
    asm("add.rn.f32x2 %0, %1, %2;" : "=l"(d) : "l"(a), "l"(b));
    return d;
}

// ---------------------------------------------------------------------------
// Phase 1: g_tanhI[bt, h] = tanh( x[bt, :] @ x2h[:, h] )
// ---------------------------------------------------------------------------
__global__ void __launch_bounds__(256) phase1_kernel(const float* __restrict__ x,
                                                     const float* __restrict__ x2h) {
    __shared__ float  x_s[16 * 132];
    __shared__ float4 w4_s[128 * 16];
    const int tid = threadIdx.x;
    const int bt0 = blockIdx.x * 16;

    for (int i = tid; i < 512; i += 256) {
        int r = i >> 5, c = i & 31;
        float4 v = *reinterpret_cast<const float4*>(x + (size_t)(bt0 + r) * NI + c * 4);
        *reinterpret_cast<float4*>(x_s + r * 132 + c * 4) = v;
    }

    const int tt = tid & 15;
    const int jc = tid >> 4;
    for (int chunk = 0; chunk < 8; ++chunk) {
        __syncthreads();
        const int jbase = chunk * 64;
        for (int i = tid; i < 2048; i += 256) {
            int k = i >> 4, jq = i & 15;
            w4_s[k * 16 + jq] =
                *reinterpret_cast<const float4*>(x2h + (size_t)k * NH + jbase + jq * 4);
        }
        __syncthreads();
        float a0 = 0.f, a1 = 0.f, a2 = 0.f, a3 = 0.f;
        #pragma unroll 8
        for (int k = 0; k < 128; ++k) {
            float  xv = x_s[tt * 132 + k];
            float4 w  = w4_s[k * 16 + jc];
            a0 = fmaf(xv, w.x, a0); a1 = fmaf(xv, w.y, a1);
            a2 = fmaf(xv, w.z, a2); a3 = fmaf(xv, w.w, a3);
        }
        float4 o = make_float4(tanhf(a0), tanhf(a1), tanhf(a2), tanhf(a3));
        *reinterpret_cast<float4*>(g_tanhI + (size_t)(bt0 + tt) * NH + jbase + jc * 4) = o;
    }
}

// ---------------------------------------------------------------------------
// Phase 2: recurrence. 16 clusters x 8 CTAs x 512 threads.
// k-pair f32x2 packing: weight float4 loads ARE the FFMA2 operands (no movs).
// hy kept m-major (hyT[m][k]) so hy loads are k-pair packed too.
//
// SMEM float layout:
//   [0)      w      64*516 = 33024   (w[j][k], j local)
//   [33024)  hyT    4*520  = 2080    (hyT[m][k])
//   [35104)  pd     256 ull = 512    (pre dup: [j][m] = {p,p})
//   [35616)  stg    10240            (stg1: 512 ents * 12 fl; stg2: 512 * 20 fl)
//   [45856)  red    8*4*64 = 2048    ([src][m][kl])
//   [47904)  hyst   4*72   = 288     ([m][kl], padded)
//   [48192)  bias   64
//   total 48256 floats = 193024 B
// ---------------------------------------------------------------------------
#define WS        516
#define HYTS      520
#define W_OFF     0
#define HYT_OFF   33024
#define PD_OFF    35104
#define STG_OFF   35616
#define RED_OFF   45856
#define HYST_OFF  47904
#define BIAS_OFF  48192
#define SMEM_FLOATS 48256
#define SMEM_BYTES  (SMEM_FLOATS * 4)

__global__ void __launch_bounds__(512)
rnn_kernel(const float* __restrict__ h2h, const float* __restrict__ bias,
           const float* __restrict__ gamma_v, const float* __restrict__ eps_v,
           float* __restrict__ out_states, float* __restrict__ out_hy) {
    extern __shared__ float sm[];
    float* bias_s = sm + BIAS_OFF;
    ull*   pd64   = reinterpret_cast<ull*>(sm + PD_OFF);

    const int tid = threadIdx.x;
    uint32_t rank;
    asm("mov.u32 %0, %%cluster_ctarank;" : "=r"(rank));
    const int m_base = (blockIdx.x >> 3) * 4;
    const int J0 = (int)rank * 64;
    const uint32_t smb = smem_u32(sm);

    // --- init: weight slice w[j][k] = h2h[k][J0+j], bias, zero hyT ---
    for (int idx = tid; idx < 64 * 512; idx += 512) {
        int k = idx >> 6, jl = idx & 63;
        sm[W_OFF + jl * WS + k] = h2h[(size_t)k * NH + J0 + jl];
    }
    if (tid < 64) bias_s[tid] = bias[J0 + tid];
    for (int i = tid; i < 4 * HYTS; i += 512) sm[HYT_OFF + i] = 0.f;

    // --- fixed thread mappings ---
    const int ks = tid >> 6;          // GEMM1 k-chunk 0..7 (64 k each)
    const int jg = tid & 63;          // GEMM1 local j
    const int js = tid >> 7;          // GEMM2 j-split 0..3 (16 j each)
    const int kq = tid & 127;         // GEMM2 & combine k-quad 0..127
    const int mc = tid >> 7;          // combine m 0..3
    const int m_u  = tid >> 6;        // update mapping (tid<256): [m][kl]
    const int kl_u = tid & 63;
    const int k_own = J0 + kl_u;
    // broadcast mapping: all 512 threads
    const int bc_r = tid >> 6, bc_m = (tid & 63) >> 4, bc_q = tid & 15;

    // hoisted DSMEM addresses
    const uint32_t red_dst = mapa_sc(smb + RED_OFF * 4, (uint32_t)(kq >> 4)) +
                             (uint32_t)((rank * 256 + mc * 64 + (kq & 15) * 4) * 4);
    const uint32_t hy_dst  = mapa_sc(smb + HYT_OFF * 4, (uint32_t)bc_r) +
                             (uint32_t)((bc_m * HYTS + J0 + bc_q * 4) * 4);

    float hy_r = 0.f, hz_r = 0.f, g_r = 0.f, e_r = 0.f, tI = 0.f;
    size_t row_base = 0;
    if (tid < 256) {
        g_r = gamma_v[k_own];
        e_r = eps_v[k_own];
        row_base = (size_t)(m_base + m_u) * T_LEN * NH + k_own;
        tI = g_tanhI[row_base];
    }

    __syncthreads();
    cluster_sync_();

    const ulonglong2* w1u = reinterpret_cast<const ulonglong2*>(sm + W_OFF + jg * WS + ks * 64);
    const ulonglong2* h0u = reinterpret_cast<const ulonglong2*>(sm + HYT_OFF + 0 * HYTS + ks * 64);
    const ulonglong2* h1u = reinterpret_cast<const ulonglong2*>(sm + HYT_OFF + 1 * HYTS + ks * 64);
    const ulonglong2* h2u = reinterpret_cast<const ulonglong2*>(sm + HYT_OFF + 2 * HYTS + ks * 64);
    const ulonglong2* h3u = reinterpret_cast<const ulonglong2*>(sm + HYT_OFF + 3 * HYTS + ks * 64);

    for (int t = 0; t < T_LEN; ++t) {
        // ---- GEMM1: k-pair packed; acc[m] = (sum_even_k, sum_odd_k) ----
        {
            ull a0 = 0, a1 = 0, a2 = 0, a3 = 0;
            #pragma unroll
            for (int i = 0; i < 16; ++i) {
                ulonglong2 wv = w1u[i];      // (w_k0,w_k1),(w_k2,w_k3)
                ulonglong2 h0 = h0u[i], h1 = h1u[i], h2 = h2u[i], h3 = h3u[i];
                ffma2(a0, h0.x, wv.x); ffma2(a0, h0.y, wv.y);
                ffma2(a1, h1.x, wv.x); ffma2(a1, h1.y, wv.y);
                ffma2(a2, h2.x, wv.x); ffma2(a2, h2.y, wv.y);
                ffma2(a3, h3.x, wv.x); ffma2(a3, h3.y, wv.y);
            }
            float* e = sm + STG_OFF + (ks * 64 + jg) * 12;
            *reinterpret_cast<ulonglong2*>(e)     = make_ulonglong2(a0, a1);
            *reinterpret_cast<ulonglong2*>(e + 4) = make_ulonglong2(a2, a3);
        }
        __syncthreads();
        // ---- reduce 8 k-chunks + horizontal + bias + tanh -> pd (dup) ----
        if (tid < 128) {
            const int j = tid >> 1, mp = tid & 1;
            ull s0 = 0, s1 = 0;
            #pragma unroll
            for (int q = 0; q < 8; ++q) {
                ulonglong2 v = *reinterpret_cast<const ulonglong2*>(
                    sm + STG_OFF + (q * 64 + j) * 12 + mp * 4);
                s0 = addf2(s0, v.x);
                s1 = addf2(s1, v.y);
            }
            float b = bias_s[j];
            float l0, h0, l1, h1;
            unpack2(l0, h0, s0);
            unpack2(l1, h1, s1);
            float p0 = tanhf(l0 + h0 + b);
            float p1 = tanhf(l1 + h1 + b);
            *reinterpret_cast<ulonglong2*>(pd64 + j * 4 + mp * 2) =
                make_ulonglong2(pack2(p0), pack2(p1));
        }
        __syncthreads();

        // ---- GEMM2: j-streamed, k-quad per thread, j-split 4 ----
        {
            ull c00 = 0, c01 = 0, c10 = 0, c11 = 0;
            ull c20 = 0, c21 = 0, c30 = 0, c31 = 0;
            const float* wbase = sm + W_OFF + (js * 16) * WS + kq * 4;
            #pragma unroll
            for (int jj = 0; jj < 16; ++jj) {
                ulonglong2 wv = *reinterpret_cast<const ulonglong2*>(wbase + jj * WS);
                const int j = js * 16 + jj;
                ulonglong2 pA = *reinterpret_cast<const ulonglong2*>(pd64 + j * 4);
                ulonglong2 pB = *reinterpret_cast<const ulonglong2*>(pd64 + j * 4 + 2);
                ffma2(c00, pA.x, wv.x); ffma2(c01, pA.x, wv.y);
                ffma2(c10, pA.y, wv.x); ffma2(c11, pA.y, wv.y);
                ffma2(c20, pB.x, wv.x); ffma2(c21, pB.x, wv.y);
                ffma2(c30, pB.y, wv.x); ffma2(c31, pB.y, wv.y);
            }
            float* e = sm + STG_OFF + (js * 128 + kq) * 20;
            *reinterpret_cast<ulonglong2*>(e)      = make_ulonglong2(c00, c01);
            *reinterpret_cast<ulonglong2*>(e + 4)  = make_ulonglong2(c10, c11);
            *reinterpret_cast<ulonglong2*>(e + 8)  = make_ulonglong2(c20, c21);
            *reinterpret_cast<ulonglong2*>(e + 12) = make_ulonglong2(c30, c31);
        }
        __syncthreads();
        // ---- combine j-splits; scatter 16B to k-owner ----
        {
            ull s0 = 0, s1 = 0;
            #pragma unroll
            for (int q = 0; q < 4; ++q) {
                ulonglong2 v = *reinterpret_cast<const ulonglong2*>(
                    sm + STG_OFF + (q * 128 + kq) * 20 + mc * 4);
                s0 = addf2(s0, v.x);
                s1 = addf2(s1, v.y);
            }
            st_dsm_v2(red_dst, s0, s1);
        }
        cluster_sync_();   // partials visible

        // ---- owner reduce + state update (tid < 256, [m][kl]) ----
        if (tid < 256) {
            int tn = (t + 1 < T_LEN) ? (t + 1) : (T_LEN - 1);
            float tI_next = g_tanhI[row_base + (size_t)tn * NH];

            float s = 0.f;
            #pragma unroll
            for (int src = 0; src < 8; ++src)
                s += sm[RED_OFF + src * 256 + m_u * 64 + kl_u];

            hz_r = hz_r + DT_C * (tI - s - g_r * hy_r - e_r * hz_r);
            hy_r = hy_r + DT_C * hz_r;
            tI = tI_next;

            out_states[(size_t)(m_base + m_u) * T_LEN * NH + (size_t)t * NH + k_own] = hy_r;
            sm[HYST_OFF + m_u * 72 + kl_u] = hy_r;
        }
        __syncthreads();

        // ---- broadcast hy slice into every rank's hyT (16B per thread) ----
        {
            ulonglong2 hv = *reinterpret_cast<const ulonglong2*>(
                sm + HYST_OFF + bc_m * 72 + bc_q * 4);
            st_dsm_v2(hy_dst, hv.x, hv.y);
        }
        cluster_sync_();   // hyT visible for next GEMM1
    }

    if (tid < 256 && out_hy)
        out_hy[(size_t)(m_base + m_u) * NH + k_own] = hy_r;
}

// ---------------------------------------------------------------------------
extern "C" void kernel_launch(void* const* d_in, const int* in_sizes, int n_in,
                              void* d_out, int out_size) {
    const float* x    = (const float*)d_in[0];
    const float* x2h  = (const float*)d_in[1];
    const float* h2h  = (const float*)d_in[2];
    const float* bias = (const float*)d_in[3];
    const float* gam  = (const float*)d_in[4];
    const float* eps  = (const float*)d_in[5];
    float* out = (float*)d_out;

    const long long BTH = (long long)BSZ * T_LEN * NH;
    float* states = nullptr;
    float* hyout  = nullptr;
    if ((long long)out_size >= BTH) {
        states = out;
        if ((long long)out_size >= BTH + (long long)BSZ * NH) hyout = out + BTH;
    } else {
        hyout = out;
    }

    phase1_kernel<<<(BSZ * T_LEN) / 16, 256>>>(x, x2h);

    cudaFuncSetAttribute(rnn_kernel, cudaFuncAttributeMaxDynamicSharedMemorySize,
                         SMEM_BYTES);

    cudaLaunchConfig_t cfg = {};
    cfg.gridDim = dim3(128, 1, 1);
    cfg.blockDim = dim3(512, 1, 1);
    cfg.dynamicSmemBytes = SMEM_BYTES;
    cfg.stream = 0;
    cudaLaunchAttribute attrs[1];
    attrs[0].id = cudaLaunchAttributeClusterDimension;
    attrs[0].val.clusterDim.x = 8;
    attrs[0].val.clusterDim.y = 1;
    attrs[0].val.clusterDim.z = 1;
    cfg.attrs = attrs;
    cfg.numAttrs = 1;
    cudaLaunchKernelEx(&cfg, rnn_kernel, h2h, bias, gam, eps, states, hyout);
}